// round 8
// baseline (speedup 1.0000x reference)
#include <cuda_runtime.h>
#include <cuda_bf16.h>
#include <cstdint>

#define BATCH   2
#define NHEADS  12
#define SEQLEN  2048
#define DMODEL  768
#define DK      64
#define MTOT    (BATCH * SEQLEN)          // 4096

typedef __nv_bfloat16 bf16;

// ---------------- scratch (no allocations allowed) ----------------
__device__ __align__(256) bf16 g_xhi[(size_t)MTOT * DMODEL];
__device__ __align__(256) bf16 g_xlo[(size_t)MTOT * DMODEL];
__device__ __align__(256) bf16 g_wqh[(size_t)3 * DMODEL * DMODEL];  // W_qkv^T [N][K]
__device__ __align__(256) bf16 g_wql[(size_t)3 * DMODEL * DMODEL];
__device__ __align__(256) bf16 g_woh[(size_t)DMODEL * DMODEL];      // W_out^T [N][K]
__device__ __align__(256) bf16 g_wol[(size_t)DMODEL * DMODEL];
__device__ __align__(256) bf16 g_qh[(size_t)BATCH * NHEADS * SEQLEN * DK];
__device__ __align__(256) bf16 g_ql[(size_t)BATCH * NHEADS * SEQLEN * DK];
__device__ __align__(256) bf16 g_kh[(size_t)BATCH * NHEADS * SEQLEN * DK];
__device__ __align__(256) bf16 g_kl[(size_t)BATCH * NHEADS * SEQLEN * DK];
__device__ __align__(256) bf16 g_vh[(size_t)BATCH * NHEADS * SEQLEN * DK];
__device__ __align__(256) bf16 g_vl[(size_t)BATCH * NHEADS * SEQLEN * DK];
__device__ __align__(256) bf16 g_ohi[(size_t)MTOT * DMODEL];
__device__ __align__(256) bf16 g_olo[(size_t)MTOT * DMODEL];

// ==================== helpers ====================
__device__ __forceinline__ uint32_t smem_u32(const void* p) {
    uint32_t a;
    asm("{ .reg .u64 t; cvta.to.shared.u64 t, %1; cvt.u32.u64 %0, t; }" : "=r"(a) : "l"(p));
    return a;
}
__device__ __forceinline__ void mma16816(float* d, const uint32_t* a, const uint32_t* b) {
    asm volatile(
        "mma.sync.aligned.m16n8k16.row.col.f32.bf16.bf16.f32 "
        "{%0,%1,%2,%3}, {%4,%5,%6,%7}, {%8,%9}, {%0,%1,%2,%3};"
        : "+f"(d[0]), "+f"(d[1]), "+f"(d[2]), "+f"(d[3])
        : "r"(a[0]), "r"(a[1]), "r"(a[2]), "r"(a[3]), "r"(b[0]), "r"(b[1]));
}
__device__ __forceinline__ void ldsm_x4(uint32_t* r, uint32_t addr) {
    asm volatile("ldmatrix.sync.aligned.m8n8.x4.shared.b16 {%0,%1,%2,%3}, [%4];"
                 : "=r"(r[0]), "=r"(r[1]), "=r"(r[2]), "=r"(r[3]) : "r"(addr));
}
__device__ __forceinline__ void ldsm_x4t(uint32_t* r, uint32_t addr) {
    asm volatile("ldmatrix.sync.aligned.m8n8.x4.trans.shared.b16 {%0,%1,%2,%3}, [%4];"
                 : "=r"(r[0]), "=r"(r[1]), "=r"(r[2]), "=r"(r[3]) : "r"(addr));
}
__device__ __forceinline__ void cp_async16(uint32_t dst, const void* src) {
    asm volatile("cp.async.cg.shared.global [%0], [%1], 16;" :: "r"(dst), "l"(src));
}
__device__ __forceinline__ void cp_commit() {
    asm volatile("cp.async.commit_group;" ::: "memory");
}
template <int N>
__device__ __forceinline__ void cp_wait() {
    asm volatile("cp.async.wait_group %0;" :: "n"(N) : "memory");
}
// split (x,y) fp32 -> packed bf16 hi pair + bf16 lo (residual) pair
__device__ __forceinline__ void split2(float x, float y, uint32_t& h, uint32_t& l) {
    __nv_bfloat162 hh = __floats2bfloat162_rn(x, y);
    float rx = x - __bfloat162float(hh.x);
    float ry = y - __bfloat162float(hh.y);
    __nv_bfloat162 ll = __floats2bfloat162_rn(rx, ry);
    h = *reinterpret_cast<uint32_t*>(&hh);
    l = *reinterpret_cast<uint32_t*>(&ll);
}

// ==================== prep kernels ====================
__global__ void split_x_kernel(const float* __restrict__ x,
                               bf16* __restrict__ hi, bf16* __restrict__ lo, int n4)
{
    int i = blockIdx.x * blockDim.x + threadIdx.x;
    if (i >= n4) return;
    float4 v = ((const float4*)x)[i];
    uint32_t h0, l0, h1, l1;
    split2(v.x, v.y, h0, l0);
    split2(v.z, v.w, h1, l1);
    ((uint32_t*)hi)[i * 2 + 0] = h0;
    ((uint32_t*)hi)[i * 2 + 1] = h1;
    ((uint32_t*)lo)[i * 2 + 0] = l0;
    ((uint32_t*)lo)[i * 2 + 1] = l1;
}

// transpose W(K,N) -> T(N,K) and split into bf16 hi/lo
__global__ void tsplit_kernel(const float* __restrict__ W,
                              bf16* __restrict__ Th, bf16* __restrict__ Tl,
                              int K, int N)
{
    __shared__ float t[32][33];
    const int tx = threadIdx.x & 31, ty = threadIdx.x >> 5;   // 256 threads
    const int bn = blockIdx.x * 32, bk = blockIdx.y * 32;
#pragma unroll
    for (int j = 0; j < 4; ++j)
        t[ty + j * 8][tx] = W[(size_t)(bk + ty + j * 8) * N + bn + tx];
    __syncthreads();
#pragma unroll
    for (int j = 0; j < 4; ++j) {
        const int n = bn + ty + j * 8;
        const int k = bk + tx;
        const float v = t[tx][ty + j * 8];
        bf16 h = __float2bfloat16(v);
        bf16 l = __float2bfloat16(v - __bfloat162float(h));
        Th[(size_t)n * K + k] = h;
        Tl[(size_t)n * K + k] = l;
    }
}

// ==================== mma.sync bf16x3 GEMM ====================
// 3-stage cp.async, ONE barrier per chunk, register-double-buffered frags.
#define GSTR 72
#define GEMM_STAGE (4 * 128 * GSTR * 2)         // 73728 B per stage
#define GEMM_SMEM  (3 * GEMM_STAGE)             // 221184 B

__device__ __forceinline__ void gemm_issue(
    uint32_t sb, int tid, const bf16* Ah, const bf16* Al,
    const bf16* Bh, const bf16* Bl, int m0, int n0, int kc, int K)
{
#pragma unroll
    for (int i = 0; i < 16; ++i) {
        const int idx = i * 256 + tid;
        const int arr = idx >> 10;
        const int rem = idx & 1023;
        const int row = rem >> 3, seg = rem & 7;
        const bf16* src = (arr == 0) ? Ah : (arr == 1) ? Al : (arr == 2) ? Bh : Bl;
        const int gr = ((arr < 2) ? m0 : n0) + row;
        cp_async16(sb + arr * 18432 + (uint32_t)(row * GSTR + seg * 8) * 2,
                   src + (size_t)gr * K + kc + seg * 8);
    }
    cp_commit();
}

template <int MODE>
__global__ __launch_bounds__(256, 1)
void gemm_mma(const bf16* __restrict__ Ah, const bf16* __restrict__ Al,
              const bf16* __restrict__ Bh, const bf16* __restrict__ Bl,
              const float* __restrict__ bias, float* __restrict__ out,
              int N, int K)
{
    extern __shared__ char smc[];
    const uint32_t base = smem_u32(smc);

    const int tid = threadIdx.x, lane = tid & 31, wid = tid >> 5;
    const int wm = wid & 3, wn = wid >> 2;
    const int m0 = blockIdx.y * 128, n0 = blockIdx.x * 128;

    float acc[2][8][4];
#pragma unroll
    for (int t = 0; t < 2; ++t)
#pragma unroll
        for (int n = 0; n < 8; ++n)
#pragma unroll
            for (int j = 0; j < 4; ++j) acc[t][n][j] = 0.f;

    const int a_r  = lane & 15;
    const int a_c8 = (lane >> 4) * 8;
    const int b_r  = (lane & 7) + ((lane >> 4) << 3);
    const int b_c8 = ((lane >> 3) & 1) * 8;

    const int NC = K / 64;                  // 12
    gemm_issue(base, tid, Ah, Al, Bh, Bl, m0, n0, 0, K);
    gemm_issue(base + GEMM_STAGE, tid, Ah, Al, Bh, Bl, m0, n0, 64, K);

    int sidx = 0;
    for (int c = 0; c < NC; ++c) {
        cp_wait<1>();        // chunk c arrived (c+1 may be pending)
        __syncthreads();     // c visible to all; stage (c-1) readers done
        if (c + 2 < NC) {
            const int s2 = (sidx + 2) % 3;   // == (c-1)%3, just freed
            gemm_issue(base + s2 * GEMM_STAGE, tid, Ah, Al, Bh, Bl,
                       m0, n0, (c + 2) * 64, K);
        }

        const uint32_t sb = base + sidx * GEMM_STAGE;

        uint32_t ahb[2][2][4], alb[2][2][4];   // A frags, dbl-buffered over kf
        auto lda = [&](int buf, int kf) {
#pragma unroll
            for (int t = 0; t < 2; ++t) {
                const uint32_t off =
                    (uint32_t)((wm * 32 + t * 16 + a_r) * GSTR + kf * 16 + a_c8) * 2;
                ldsm_x4(ahb[buf][t], sb + off);
                ldsm_x4(alb[buf][t], sb + 18432 + off);
            }
        };
        lda(0, 0);
#pragma unroll
        for (int kf = 0; kf < 4; ++kf) {
            const int ab = kf & 1;
            if (kf < 3) lda(ab ^ 1, kf + 1);

            uint32_t bhb[2][4], blb[2][4];     // B frags, dbl-buffered over nt2
            auto ldb = [&](int buf, int nt2) {
                const uint32_t off =
                    (uint32_t)((wn * 64 + nt2 * 16 + b_r) * GSTR + kf * 16 + b_c8) * 2;
                ldsm_x4(bhb[buf], sb + 36864 + off);
                ldsm_x4(blb[buf], sb + 55296 + off);
            };
            ldb(0, 0);
#pragma unroll
            for (int nt2 = 0; nt2 < 4; ++nt2) {
                const int bb = nt2 & 1;
                if (nt2 < 3) ldb(bb ^ 1, nt2 + 1);
#pragma unroll
                for (int t = 0; t < 2; ++t)
#pragma unroll
                    for (int h = 0; h < 2; ++h) {
                        float* d = acc[t][nt2 * 2 + h];
                        mma16816(d, ahb[ab][t], bhb[bb] + h * 2);
                        mma16816(d, ahb[ab][t], blb[bb] + h * 2);
                        mma16816(d, alb[ab][t], bhb[bb] + h * 2);
                    }
            }
        }
        sidx = (sidx == 2) ? 0 : sidx + 1;
    }

    // epilogue
#pragma unroll
    for (int t = 0; t < 2; ++t) {
        const int gr0 = m0 + wm * 32 + t * 16 + (lane >> 2);
#pragma unroll
        for (int nt = 0; nt < 8; ++nt) {
            const int gn = n0 + wn * 64 + nt * 8 + 2 * (lane & 3);
            const float b0 = bias[gn], b1 = bias[gn + 1];
            const float v00 = acc[t][nt][0] + b0, v01 = acc[t][nt][1] + b1;
            const float v10 = acc[t][nt][2] + b0, v11 = acc[t][nt][3] + b1;
            if (MODE == 0) {
                *(float2*)&out[(size_t)gr0 * N + gn]       = make_float2(v00, v01);
                *(float2*)&out[(size_t)(gr0 + 8) * N + gn] = make_float2(v10, v11);
            } else {
                const int part = gn / DMODEL;
                const int w = gn % DMODEL;
                const int hh = w >> 6, dd = w & 63;
                bf16* dh = (part == 0) ? g_qh : (part == 1) ? g_kh : g_vh;
                bf16* dl = (part == 0) ? g_ql : (part == 1) ? g_kl : g_vl;
                const int bb = gr0 >> 11;
                const int ll0 = gr0 & 2047;
                const size_t i0 = (((size_t)bb * NHEADS + hh) * SEQLEN + ll0) * DK + dd;
                const size_t i1 = i0 + 8 * DK;
                uint32_t ph, pl;
                split2(v00, v01, ph, pl);
                *(uint32_t*)(dh + i0) = ph; *(uint32_t*)(dl + i0) = pl;
                split2(v10, v11, ph, pl);
                *(uint32_t*)(dh + i1) = ph; *(uint32_t*)(dl + i1) = pl;
            }
        }
    }
}

// ==================== flash attention: in-warp softmax/MMA pipeline ====
// BM=128, BN=64, 256 thr / 8 warps. 3 KV stages, ONE barrier per iter.
// Iter it: issue S-mma(it) -> sNxt; softmax(it-1) on sCur; PV(it-1);
//          cp_wait; barrier; issue KV(it+2).
#define KV_STG   36864
#define ATT_Q    0
#define ATT_KV   36864
#define ATT_MASK (36864 + 3 * KV_STG)            // 147456
#define ATT_SMEM (ATT_MASK + 3 * 256)            // 148224

__device__ __forceinline__ void attn_issue_kv(
    uint32_t base, int tid, const bf16* Kh, const bf16* Kl,
    const bf16* Vh, const bf16* Vl, const int* amask_row, int kb, int stg)
{
    const uint32_t sb = base + ATT_KV + stg * KV_STG;
#pragma unroll
    for (int i = 0; i < 8; ++i) {
        const int idx = i * 256 + tid;      // 4 arrays x 512
        const int arr = idx >> 9;
        const int rem = idx & 511;
        const int row = rem >> 3, seg = rem & 7;
        const bf16* src = (arr == 0) ? Kh : (arr == 1) ? Kl : (arr == 2) ? Vh : Vl;
        cp_async16(sb + arr * 9216 + (uint32_t)(row * GSTR + seg * 8) * 2,
                   src + (size_t)(kb + row) * DK + seg * 8);
    }
    if (tid < 16)
        cp_async16(base + ATT_MASK + stg * 256 + tid * 16, amask_row + kb + tid * 4);
    cp_commit();
}

__global__ __launch_bounds__(256, 1)
void attn_mma(const int* __restrict__ amask)
{
    extern __shared__ char smc[];
    const uint32_t base = smem_u32(smc);

    const int tid = threadIdx.x, lane = tid & 31, wid = tid >> 5;
    const int bh = blockIdx.y, b = bh / NHEADS, h = bh % NHEADS;
    const int qb = blockIdx.x * 128;

    const bf16* Qh = g_qh + (size_t)bh * SEQLEN * DK;
    const bf16* Ql = g_ql + (size_t)bh * SEQLEN * DK;
    const bf16* Kh = g_kh + (size_t)bh * SEQLEN * DK;
    const bf16* Kl = g_kl + (size_t)bh * SEQLEN * DK;
    const bf16* Vh = g_vh + (size_t)bh * SEQLEN * DK;
    const bf16* Vl = g_vl + (size_t)bh * SEQLEN * DK;
    const int* amask_row = amask + (size_t)b * SEQLEN;

    // prologue: G0 = Q + KV0 + mask0 (one group)
#pragma unroll
    for (int i = 0; i < 8; ++i) {
        const int idx = i * 256 + tid;
        const int arr = idx >> 10;
        const int rem = idx & 1023;
        const int row = rem >> 3, seg = rem & 7;
        const bf16* src = arr ? Ql : Qh;
        cp_async16(base + ATT_Q + arr * 18432 + (uint32_t)(row * GSTR + seg * 8) * 2,
                   src + (size_t)(qb + row) * DK + seg * 8);
    }
    attn_issue_kv(base, tid, Kh, Kl, Vh, Vl, amask_row, 0, 0);   // commits G0
    attn_issue_kv(base, tid, Kh, Kl, Vh, Vl, amask_row, 64, 1);  // G1

    float m0s = -1e30f, m1s = -1e30f, l0s = 0.f, l1s = 0.f;
    float oacc[8][4];
#pragma unroll
    for (int n = 0; n < 8; ++n)
#pragma unroll
        for (int j = 0; j < 4; ++j) oacc[n][j] = 0.f;

    const int a_r  = lane & 15;
    const int a_c8 = (lane >> 4) * 8;
    const int kb_r = (lane & 7) + ((lane >> 4) << 3);
    const int kb_c8 = ((lane >> 3) & 1) * 8;
    const int vb_r = (lane & 7) + ((lane >> 3) & 1) * 8;
    const int vb_c8 = (lane >> 4) * 8;
    const int mrow = wid * 16;
    const int cbase = 2 * (lane & 3);
    const int NIT = SEQLEN / 64;   // 32

    float sA[8][4], sB[8][4];

    // S = Q @ K^T for block `it`, into sN, from KV stage stg
    auto smma = [&](float (&sN)[8][4], int stg) {
#pragma unroll
        for (int n = 0; n < 8; ++n)
#pragma unroll
            for (int j = 0; j < 4; ++j) sN[n][j] = 0.f;
        const uint32_t kvb = base + ATT_KV + stg * KV_STG;
#pragma unroll
        for (int kf = 0; kf < 4; ++kf) {
            uint32_t qh4[4], ql4[4];
            const uint32_t qoff = (uint32_t)((mrow + a_r) * GSTR + kf * 16 + a_c8) * 2;
            ldsm_x4(qh4, base + ATT_Q + qoff);
            ldsm_x4(ql4, base + ATT_Q + 18432 + qoff);
#pragma unroll
            for (int nt2 = 0; nt2 < 4; ++nt2) {
                const uint32_t koff =
                    (uint32_t)((nt2 * 16 + kb_r) * GSTR + kf * 16 + kb_c8) * 2;
                uint32_t kh4[4], kl4[4];
                ldsm_x4(kh4, kvb + koff);
                ldsm_x4(kl4, kvb + 9216 + koff);
#pragma unroll
                for (int hh = 0; hh < 2; ++hh) {
                    float* d = sN[nt2 * 2 + hh];
                    mma16816(d, qh4, kh4 + hh * 2);
                    mma16816(d, qh4, kl4 + hh * 2);
                    mma16816(d, ql4, kh4 + hh * 2);
                }
            }
        }
    };

    // softmax + PV for block whose S is in sC (KV stage stg)
    auto softpv = [&](float (&sC)[8][4], int stg) {
        const int* smask = (const int*)(smc + ATT_MASK + stg * 256);
        const uint32_t kvb = base + ATT_KV + stg * KV_STG;
#pragma unroll
        for (int nt = 0; nt < 8; ++nt) {
            const float ma = smask[nt * 8 + cbase]     ? 0.f : -1e30f;
            const float mb = smask[nt * 8 + cbase + 1] ? 0.f : -1e30f;
            sC[nt][0] = sC[nt][0] * 0.125f + ma;
            sC[nt][1] = sC[nt][1] * 0.125f + mb;
            sC[nt][2] = sC[nt][2] * 0.125f + ma;
            sC[nt][3] = sC[nt][3] * 0.125f + mb;
        }
        float mx0 = -1e30f, mx1 = -1e30f;
#pragma unroll
        for (int nt = 0; nt < 8; ++nt) {
            mx0 = fmaxf(mx0, fmaxf(sC[nt][0], sC[nt][1]));
            mx1 = fmaxf(mx1, fmaxf(sC[nt][2], sC[nt][3]));
        }
        mx0 = fmaxf(mx0, __shfl_xor_sync(0xffffffffu, mx0, 1));
        mx0 = fmaxf(mx0, __shfl_xor_sync(0xffffffffu, mx0, 2));
        mx1 = fmaxf(mx1, __shfl_xor_sync(0xffffffffu, mx1, 1));
        mx1 = fmaxf(mx1, __shfl_xor_sync(0xffffffffu, mx1, 2));
        const float mn0 = fmaxf(m0s, mx0), mn1 = fmaxf(m1s, mx1);
        const float al0 = __expf(m0s - mn0), al1 = __expf(m1s - mn1);
        m0s = mn0; m1s = mn1;
        float rs0 = 0.f, rs1 = 0.f;
#pragma unroll
        for (int nt = 0; nt < 8; ++nt) {
            sC[nt][0] = __expf(sC[nt][0] - mn0);
            sC[nt][1] = __expf(sC[nt][1] - mn0);
            sC[nt][2] = __expf(sC[nt][2] - mn1);
            sC[nt][3] = __expf(sC[nt][3] - mn1);
            rs0 += sC[nt][0] + sC[nt][1];
            rs1 += sC[nt][2] + sC[nt][3];
        }
        rs0 += __shfl_xor_sync(0xffffffffu, rs0, 1);
        rs0 += __shfl_xor_sync(0xffffffffu, rs0, 2);
        rs1 += __shfl_xor_sync(0xffffffffu, rs1, 1);
        rs1 += __shfl_xor_sync(0xffffffffu, rs1, 2);
        l0s = l0s * al0 + rs0;
        l1s = l1s * al1 + rs1;
#pragma unroll
        for (int nt = 0; nt < 8; ++nt) {
            oacc[nt][0] *= al0; oacc[nt][1] *= al0;
            oacc[nt][2] *= al1; oacc[nt][3] *= al1;
        }
#pragma unroll
        for (int kf2 = 0; kf2 < 4; ++kf2) {
            uint32_t ph4[4], pl4[4];
            split2(sC[2 * kf2][0],     sC[2 * kf2][1],     ph4[0], pl4[0]);
            split2(sC[2 * kf2][2],     sC[2 * kf2][3],     ph4[1], pl4[1]);
            split2(sC[2 * kf2 + 1][0], sC[2 * kf2 + 1][1], ph4[2], pl4[2]);
            split2(sC[2 * kf2 + 1][2], sC[2 * kf2 + 1][3], ph4[3], pl4[3]);
#pragma unroll
            for (int dt2 = 0; dt2 < 4; ++dt2) {
                const uint32_t voff =
                    (uint32_t)((kf2 * 16 + vb_r) * GSTR + dt2 * 16 + vb_c8) * 2;
                uint32_t vh4[4], vl4[4];
                ldsm_x4t(vh4, kvb + 18432 + voff);
                ldsm_x4t(vl4, kvb + 27648 + voff);
#pragma unroll
                for (int hh = 0; hh < 2; ++hh) {
                    float* d = oacc[dt2 * 2 + hh];
                    mma16816(d, ph4, vh4 + hh * 2);
                    mma16816(d, ph4, vl4 + hh * 2);
                    mma16816(d, pl4, vh4 + hh * 2);
                }
            }
        }
    };

    auto mgmt = [&](int it) {
        cp_wait<0>();
        __syncthreads();
        if (it + 2 < NIT)
            attn_issue_kv(base, tid, Kh, Kl, Vh, Vl, amask_row,
                          (it + 2) * 64, (it + 2) % 3);
    };

    // prologue finish: wait G0,G1; issue KV2; compute S(0)
    cp_wait<0>();
    __syncthreads();
    attn_issue_kv(base, tid, Kh, Kl, Vh, Vl, amask_row, 128, 2);  // G2
    smma(sA, 0);

    for (int it = 1; it + 1 < NIT; it += 2) {
        smma(sB, it % 3);        softpv(sA, (it - 1) % 3);  mgmt(it);
        smma(sA, (it + 1) % 3);  softpv(sB, it % 3);        mgmt(it + 1);
    }
    // tail: it = NIT-1 (odd since NIT even)
    smma(sB, (NIT - 1) % 3);
    softpv(sA, (NIT - 2) % 3);
    mgmt(NIT - 1);
    softpv(sB, (NIT - 1) % 3);

    // epilogue: O /= l, split to bf16 hi/lo, write (B,L,D)
    const float inv0 = 1.f / l0s, inv1 = 1.f / l1s;
    const int row0 = qb + mrow + (lane >> 2);
#pragma unroll
    for (int dt = 0; dt < 8; ++dt) {
        const int col = h * DK + dt * 8 + 2 * (lane & 3);
        const size_t i0 = ((size_t)b * SEQLEN + row0) * DMODEL + col;
        const size_t i1 = i0 + (size_t)8 * DMODEL;
        uint32_t hh, ll;
        split2(oacc[dt][0] * inv0, oacc[dt][1] * inv0, hh, ll);
        *(uint32_t*)(g_ohi + i0) = hh; *(uint32_t*)(g_olo + i0) = ll;
        split2(oacc[dt][2] * inv1, oacc[dt][3] * inv1, hh, ll);
        *(uint32_t*)(g_ohi + i1) = hh; *(uint32_t*)(g_olo + i1) = ll;
    }
}

// ==================== launch ====================
extern "C" void kernel_launch(void* const* d_in, const int* in_sizes, int n_in,
                              void* d_out, int out_size)
{
    const float* x     = (const float*)d_in[0];
    const int*   amask = (const int*)  d_in[1];
    const float* w_qkv = (const float*)d_in[2];
    const float* b_qkv = (const float*)d_in[3];
    const float* w_out = (const float*)d_in[4];
    const float* b_out = (const float*)d_in[5];
    float*       out   = (float*)d_out;

    bf16 *xhi, *xlo, *wqh, *wql, *woh, *wol, *ohi, *olo;
    cudaGetSymbolAddress((void**)&xhi, g_xhi);
    cudaGetSymbolAddress((void**)&xlo, g_xlo);
    cudaGetSymbolAddress((void**)&wqh, g_wqh);
    cudaGetSymbolAddress((void**)&wql, g_wql);
    cudaGetSymbolAddress((void**)&woh, g_woh);
    cudaGetSymbolAddress((void**)&wol, g_wol);
    cudaGetSymbolAddress((void**)&ohi, g_ohi);
    cudaGetSymbolAddress((void**)&olo, g_olo);

    // 0) splits / transposes
    const int n4 = MTOT * DMODEL / 4;
    split_x_kernel<<<(n4 + 255) / 256, 256>>>(x, xhi, xlo, n4);
    tsplit_kernel<<<dim3(3 * DMODEL / 32, DMODEL / 32), 256>>>(w_qkv, wqh, wql, DMODEL, 3 * DMODEL);
    tsplit_kernel<<<dim3(DMODEL / 32, DMODEL / 32), 256>>>(w_out, woh, wol, DMODEL, DMODEL);

    // 1) QKV projection
    cudaFuncSetAttribute(gemm_mma<1>, cudaFuncAttributeMaxDynamicSharedMemorySize, GEMM_SMEM);
    gemm_mma<1><<<dim3(3 * DMODEL / 128, MTOT / 128), 256, GEMM_SMEM>>>(
        xhi, xlo, wqh, wql, b_qkv, nullptr, 3 * DMODEL, DMODEL);

    // 2) flash attention
    cudaFuncSetAttribute(attn_mma, cudaFuncAttributeMaxDynamicSharedMemorySize, ATT_SMEM);
    attn_mma<<<dim3(SEQLEN / 128, BATCH * NHEADS), 256, ATT_SMEM>>>(amask);

    // 3) output projection
    cudaFuncSetAttribute(gemm_mma<0>, cudaFuncAttributeMaxDynamicSharedMemorySize, GEMM_SMEM);
    gemm_mma<0><<<dim3(DMODEL / 128, MTOT / 128), 256, GEMM_SMEM>>>(
        ohi, olo, woh, wol, b_out, out, DMODEL, DMODEL);
}

// round 9
// speedup vs baseline: 1.0803x; 1.0803x over previous
#include <cuda_runtime.h>
#include <cuda_bf16.h>
#include <cstdint>

#define BATCH   2
#define NHEADS  12
#define SEQLEN  2048
#define DMODEL  768
#define DK      64
#define MTOT    (BATCH * SEQLEN)          // 4096

typedef __nv_bfloat16 bf16;

// ---------------- scratch (no allocations allowed) ----------------
__device__ __align__(256) bf16 g_xhi[(size_t)MTOT * DMODEL];
__device__ __align__(256) bf16 g_xlo[(size_t)MTOT * DMODEL];
__device__ __align__(256) bf16 g_wqh[(size_t)3 * DMODEL * DMODEL];  // W_qkv^T [N][K]
__device__ __align__(256) bf16 g_wql[(size_t)3 * DMODEL * DMODEL];
__device__ __align__(256) bf16 g_woh[(size_t)DMODEL * DMODEL];      // W_out^T [N][K]
__device__ __align__(256) bf16 g_wol[(size_t)DMODEL * DMODEL];
__device__ __align__(256) bf16 g_qh[(size_t)BATCH * NHEADS * SEQLEN * DK];
__device__ __align__(256) bf16 g_ql[(size_t)BATCH * NHEADS * SEQLEN * DK];
__device__ __align__(256) bf16 g_kh[(size_t)BATCH * NHEADS * SEQLEN * DK];
__device__ __align__(256) bf16 g_kl[(size_t)BATCH * NHEADS * SEQLEN * DK];
__device__ __align__(256) bf16 g_vh[(size_t)BATCH * NHEADS * SEQLEN * DK];
__device__ __align__(256) bf16 g_vl[(size_t)BATCH * NHEADS * SEQLEN * DK];
__device__ __align__(256) bf16 g_ohi[(size_t)MTOT * DMODEL];
__device__ __align__(256) bf16 g_olo[(size_t)MTOT * DMODEL];

// ==================== helpers ====================
__device__ __forceinline__ uint32_t smem_u32(const void* p) {
    uint32_t a;
    asm("{ .reg .u64 t; cvta.to.shared.u64 t, %1; cvt.u32.u64 %0, t; }" : "=r"(a) : "l"(p));
    return a;
}
__device__ __forceinline__ void mma16816(float* d, const uint32_t* a, const uint32_t* b) {
    asm volatile(
        "mma.sync.aligned.m16n8k16.row.col.f32.bf16.bf16.f32 "
        "{%0,%1,%2,%3}, {%4,%5,%6,%7}, {%8,%9}, {%0,%1,%2,%3};"
        : "+f"(d[0]), "+f"(d[1]), "+f"(d[2]), "+f"(d[3])
        : "r"(a[0]), "r"(a[1]), "r"(a[2]), "r"(a[3]), "r"(b[0]), "r"(b[1]));
}
__device__ __forceinline__ void ldsm_x4(uint32_t* r, uint32_t addr) {
    asm volatile("ldmatrix.sync.aligned.m8n8.x4.shared.b16 {%0,%1,%2,%3}, [%4];"
                 : "=r"(r[0]), "=r"(r[1]), "=r"(r[2]), "=r"(r[3]) : "r"(addr));
}
__device__ __forceinline__ void ldsm_x4t(uint32_t* r, uint32_t addr) {
    asm volatile("ldmatrix.sync.aligned.m8n8.x4.trans.shared.b16 {%0,%1,%2,%3}, [%4];"
                 : "=r"(r[0]), "=r"(r[1]), "=r"(r[2]), "=r"(r[3]) : "r"(addr));
}
__device__ __forceinline__ void cp_async16(uint32_t dst, const void* src) {
    asm volatile("cp.async.cg.shared.global [%0], [%1], 16;" :: "r"(dst), "l"(src));
}
__device__ __forceinline__ void cp_commit() {
    asm volatile("cp.async.commit_group;" ::: "memory");
}
template <int N>
__device__ __forceinline__ void cp_wait() {
    asm volatile("cp.async.wait_group %0;" :: "n"(N) : "memory");
}
// split (x,y) fp32 -> packed bf16 hi pair + bf16 lo (residual) pair
__device__ __forceinline__ void split2(float x, float y, uint32_t& h, uint32_t& l) {
    __nv_bfloat162 hh = __floats2bfloat162_rn(x, y);
    float rx = x - __bfloat162float(hh.x);
    float ry = y - __bfloat162float(hh.y);
    __nv_bfloat162 ll = __floats2bfloat162_rn(rx, ry);
    h = *reinterpret_cast<uint32_t*>(&hh);
    l = *reinterpret_cast<uint32_t*>(&ll);
}

// ==================== prep kernels ====================
__global__ void split_x_kernel(const float* __restrict__ x,
                               bf16* __restrict__ hi, bf16* __restrict__ lo, int n4)
{
    int i = blockIdx.x * blockDim.x + threadIdx.x;
    if (i >= n4) return;
    float4 v = ((const float4*)x)[i];
    uint32_t h0, l0, h1, l1;
    split2(v.x, v.y, h0, l0);
    split2(v.z, v.w, h1, l1);
    ((uint32_t*)hi)[i * 2 + 0] = h0;
    ((uint32_t*)hi)[i * 2 + 1] = h1;
    ((uint32_t*)lo)[i * 2 + 0] = l0;
    ((uint32_t*)lo)[i * 2 + 1] = l1;
}

// transpose W(K,N) -> T(N,K) and split into bf16 hi/lo
__global__ void tsplit_kernel(const float* __restrict__ W,
                              bf16* __restrict__ Th, bf16* __restrict__ Tl,
                              int K, int N)
{
    __shared__ float t[32][33];
    const int tx = threadIdx.x & 31, ty = threadIdx.x >> 5;   // 256 threads
    const int bn = blockIdx.x * 32, bk = blockIdx.y * 32;
#pragma unroll
    for (int j = 0; j < 4; ++j)
        t[ty + j * 8][tx] = W[(size_t)(bk + ty + j * 8) * N + bn + tx];
    __syncthreads();
#pragma unroll
    for (int j = 0; j < 4; ++j) {
        const int n = bn + ty + j * 8;
        const int k = bk + tx;
        const float v = t[tx][ty + j * 8];
        bf16 h = __float2bfloat16(v);
        bf16 l = __float2bfloat16(v - __bfloat162float(h));
        Th[(size_t)n * K + k] = h;
        Tl[(size_t)n * K + k] = l;
    }
}

// ==================== mma.sync bf16x3 GEMM (128x64 tile, occ 2) =========
// C(M,N) = (Ah+Al)(M,K) @ (Bh+Bl)(N,K)^T + bias, fp32 accum.
// 128x64 CTA tile, 8 warps (4m x 2n), warp tile 32x32, k-chunk 64,
// 2 cp.async stages, 2 CTAs/SM.
#define GSTR 72
#define G_STAGE 55296                     // Ah 0 | Al 18432 | Bh 36864 | Bl 46080
#define G_SMEM  (2 * G_STAGE)             // 110592 B

__device__ __forceinline__ void gemm_issue(
    uint32_t sb, int tid, const bf16* Ah, const bf16* Al,
    const bf16* Bh, const bf16* Bl, int m0, int n0, int kc, int K)
{
#pragma unroll
    for (int i = 0; i < 12; ++i) {
        const int idx = i * 256 + tid;       // 0..3071
        uint32_t dst; const bf16* src; int grow, seg;
        if (idx < 2048) {                    // A hi/lo: 2 arrays x 1024
            const int arr = idx >> 10, rem = idx & 1023;
            const int row = rem >> 3; seg = rem & 7;
            src = arr ? Al : Ah; grow = m0 + row;
            dst = sb + arr * 18432 + (uint32_t)(row * GSTR + seg * 8) * 2;
        } else {                             // B hi/lo: 2 arrays x 512
            const int j = idx - 2048;
            const int arr = j >> 9, rem = j & 511;
            const int row = rem >> 3; seg = rem & 7;
            src = arr ? Bl : Bh; grow = n0 + row;
            dst = sb + 36864 + arr * 9216 + (uint32_t)(row * GSTR + seg * 8) * 2;
        }
        cp_async16(dst, src + (size_t)grow * K + kc + seg * 8);
    }
    cp_commit();
}

template <int MODE>
__global__ __launch_bounds__(256, 2)
void gemm_mma(const bf16* __restrict__ Ah, const bf16* __restrict__ Al,
              const bf16* __restrict__ Bh, const bf16* __restrict__ Bl,
              const float* __restrict__ bias, float* __restrict__ out,
              int N, int K)
{
    extern __shared__ char smc[];
    const uint32_t base = smem_u32(smc);

    const int tid = threadIdx.x, lane = tid & 31, wid = tid >> 5;
    const int wm = wid & 3, wn = wid >> 2;        // 4m x 2n
    const int m0 = blockIdx.y * 128, n0 = blockIdx.x * 64;

    float acc[2][4][4];
#pragma unroll
    for (int t = 0; t < 2; ++t)
#pragma unroll
        for (int n = 0; n < 4; ++n)
#pragma unroll
            for (int j = 0; j < 4; ++j) acc[t][n][j] = 0.f;

    const int a_r  = lane & 15;
    const int a_c8 = (lane >> 4) * 8;
    const int b_r  = (lane & 7) + ((lane >> 4) << 3);
    const int b_c8 = ((lane >> 3) & 1) * 8;

    const int NC = K / 64;                  // 12
    gemm_issue(base, tid, Ah, Al, Bh, Bl, m0, n0, 0, K);   // G0 -> stage 0

    for (int c = 0; c < NC; ++c) {
        const int buf = c & 1;
        if (c + 1 < NC) {
            gemm_issue(base + (buf ^ 1) * G_STAGE, tid, Ah, Al, Bh, Bl,
                       m0, n0, (c + 1) * 64, K);
            cp_wait<1>();
        } else {
            cp_wait<0>();
        }
        __syncthreads();

        const uint32_t sb = base + buf * G_STAGE;
#pragma unroll
        for (int kf = 0; kf < 4; ++kf) {
            uint32_t ah[2][4], al[2][4];
#pragma unroll
            for (int t = 0; t < 2; ++t) {
                const uint32_t off =
                    (uint32_t)((wm * 32 + t * 16 + a_r) * GSTR + kf * 16 + a_c8) * 2;
                ldsm_x4(ah[t], sb + off);
                ldsm_x4(al[t], sb + 18432 + off);
            }
#pragma unroll
            for (int nt2 = 0; nt2 < 2; ++nt2) {
                const uint32_t off =
                    (uint32_t)((wn * 32 + nt2 * 16 + b_r) * GSTR + kf * 16 + b_c8) * 2;
                uint32_t bh4[4], bl4[4];
                ldsm_x4(bh4, sb + 36864 + off);
                ldsm_x4(bl4, sb + 46080 + off);
#pragma unroll
                for (int t = 0; t < 2; ++t)
#pragma unroll
                    for (int h = 0; h < 2; ++h) {
                        float* d = acc[t][nt2 * 2 + h];
                        mma16816(d, ah[t], bh4 + h * 2);
                        mma16816(d, ah[t], bl4 + h * 2);
                        mma16816(d, al[t], bh4 + h * 2);
                    }
            }
        }
        __syncthreads();   // readers done before this stage is refilled
    }

    // epilogue
#pragma unroll
    for (int t = 0; t < 2; ++t) {
        const int gr0 = m0 + wm * 32 + t * 16 + (lane >> 2);
#pragma unroll
        for (int nt = 0; nt < 4; ++nt) {
            const int gn = n0 + wn * 32 + nt * 8 + 2 * (lane & 3);
            const float b0 = bias[gn], b1 = bias[gn + 1];
            const float v00 = acc[t][nt][0] + b0, v01 = acc[t][nt][1] + b1;
            const float v10 = acc[t][nt][2] + b0, v11 = acc[t][nt][3] + b1;
            if (MODE == 0) {
                *(float2*)&out[(size_t)gr0 * N + gn]       = make_float2(v00, v01);
                *(float2*)&out[(size_t)(gr0 + 8) * N + gn] = make_float2(v10, v11);
            } else {
                const int part = gn / DMODEL;
                const int w = gn % DMODEL;
                const int hh = w >> 6, dd = w & 63;
                bf16* dh = (part == 0) ? g_qh : (part == 1) ? g_kh : g_vh;
                bf16* dl = (part == 0) ? g_ql : (part == 1) ? g_kl : g_vl;
                const int bb = gr0 >> 11;
                const int ll0 = gr0 & 2047;
                const size_t i0 = (((size_t)bb * NHEADS + hh) * SEQLEN + ll0) * DK + dd;
                const size_t i1 = i0 + 8 * DK;
                uint32_t ph, pl;
                split2(v00, v01, ph, pl);
                *(uint32_t*)(dh + i0) = ph; *(uint32_t*)(dl + i0) = pl;
                split2(v10, v11, ph, pl);
                *(uint32_t*)(dh + i1) = ph; *(uint32_t*)(dl + i1) = pl;
            }
        }
    }
}

// ==================== flash attention via mma.sync (bf16x3, occ 2) ======
// BM=128, BN=64, dk=64, 256 thr / 8 warps; warp owns 16 rows.
// 2 KV stages, one barrier/iter, exp2-domain softmax.
// smem: Qh 0, Ql 18432 | KV stage s at 36864+s*36864 | mask ints 110592+s*256
#define KV_STAGE  36864
#define ATT_MASK  110592
#define ATT_SMEM  (110592 + 512)
#define SCALE_L2E 0.1803368867f           // 0.125 * log2(e)

__device__ __forceinline__ void attn_issue_kv(
    uint32_t base, int tid, const bf16* Kh, const bf16* Kl,
    const bf16* Vh, const bf16* Vl, const int* amask_row, int kb, int buf)
{
    const uint32_t sb = base + 36864 + buf * KV_STAGE;
#pragma unroll
    for (int i = 0; i < 8; ++i) {
        const int idx = i * 256 + tid;      // 4 arrays x 512
        const int arr = idx >> 9;
        const int rem = idx & 511;
        const int row = rem >> 3, seg = rem & 7;
        const bf16* src = (arr == 0) ? Kh : (arr == 1) ? Kl : (arr == 2) ? Vh : Vl;
        cp_async16(sb + arr * 9216 + (uint32_t)(row * GSTR + seg * 8) * 2,
                   src + (size_t)(kb + row) * DK + seg * 8);
    }
    if (tid < 16)
        cp_async16(base + ATT_MASK + buf * 256 + tid * 16, amask_row + kb + tid * 4);
    cp_commit();
}

__global__ __launch_bounds__(256, 2)
void attn_mma(const int* __restrict__ amask)
{
    extern __shared__ char smc[];
    const uint32_t base = smem_u32(smc);

    const int tid = threadIdx.x, lane = tid & 31, wid = tid >> 5;
    const int bh = blockIdx.y, b = bh / NHEADS, h = bh % NHEADS;
    const int qb = blockIdx.x * 128;

    const bf16* Qh = g_qh + (size_t)bh * SEQLEN * DK;
    const bf16* Ql = g_ql + (size_t)bh * SEQLEN * DK;
    const bf16* Kh = g_kh + (size_t)bh * SEQLEN * DK;
    const bf16* Kl = g_kl + (size_t)bh * SEQLEN * DK;
    const bf16* Vh = g_vh + (size_t)bh * SEQLEN * DK;
    const bf16* Vl = g_vl + (size_t)bh * SEQLEN * DK;
    const int* amask_row = amask + (size_t)b * SEQLEN;

    // prologue G0: Q (hi/lo) + KV chunk 0 + mask 0 (single commit)
#pragma unroll
    for (int i = 0; i < 8; ++i) {
        const int idx = i * 256 + tid;          // 0..2047
        const int arr = idx >> 10;              // 0 hi, 1 lo
        const int rem = idx & 1023;
        const int row = rem >> 3, seg = rem & 7;
        const bf16* src = arr ? Ql : Qh;
        cp_async16(base + arr * 18432 + (uint32_t)(row * GSTR + seg * 8) * 2,
                   src + (size_t)(qb + row) * DK + seg * 8);
    }
    attn_issue_kv(base, tid, Kh, Kl, Vh, Vl, amask_row, 0, 0);

    float m0s = -1e30f, m1s = -1e30f, l0s = 0.f, l1s = 0.f;
    float oacc[8][4];
#pragma unroll
    for (int n = 0; n < 8; ++n)
#pragma unroll
        for (int j = 0; j < 4; ++j) oacc[n][j] = 0.f;

    const int a_r  = lane & 15;
    const int a_c8 = (lane >> 4) * 8;
    const int kb_r = (lane & 7) + ((lane >> 4) << 3);
    const int kb_c8 = ((lane >> 3) & 1) * 8;
    const int vb_r = (lane & 7) + ((lane >> 3) & 1) * 8;
    const int vb_c8 = (lane >> 4) * 8;
    const int mrow = wid * 16;
    const int cbase = 2 * (lane & 3);

    const int NIT = SEQLEN / 64;   // 32
    for (int it = 0; it < NIT; ++it) {
        const int buf = it & 1;
        if (it + 1 < NIT) {
            attn_issue_kv(base, tid, Kh, Kl, Vh, Vl, amask_row, (it + 1) * 64, buf ^ 1);
            cp_wait<1>();
        } else {
            cp_wait<0>();
        }
        __syncthreads();

        const uint32_t kvb = base + 36864 + buf * KV_STAGE;
        const int* smask = (const int*)(smc + ATT_MASK + buf * 256);

        // ---- S = Q @ K^T ----
        float sacc[8][4];
#pragma unroll
        for (int n = 0; n < 8; ++n)
#pragma unroll
            for (int j = 0; j < 4; ++j) sacc[n][j] = 0.f;

#pragma unroll
        for (int kf = 0; kf < 4; ++kf) {
            uint32_t qh4[4], ql4[4];
            const uint32_t qoff = (uint32_t)((mrow + a_r) * GSTR + kf * 16 + a_c8) * 2;
            ldsm_x4(qh4, base + qoff);
            ldsm_x4(ql4, base + 18432 + qoff);
#pragma unroll
            for (int nt2 = 0; nt2 < 4; ++nt2) {
                const uint32_t koff =
                    (uint32_t)((nt2 * 16 + kb_r) * GSTR + kf * 16 + kb_c8) * 2;
                uint32_t kh4[4], kl4[4];
                ldsm_x4(kh4, kvb + koff);
                ldsm_x4(kl4, kvb + 9216 + koff);
#pragma unroll
                for (int hh = 0; hh < 2; ++hh) {
                    float* d = sacc[nt2 * 2 + hh];
                    mma16816(d, qh4, kh4 + hh * 2);
                    mma16816(d, qh4, kl4 + hh * 2);
                    mma16816(d, ql4, kh4 + hh * 2);
                }
            }
        }

        // ---- scale (log2 domain) + mask ----
#pragma unroll
        for (int nt = 0; nt < 8; ++nt) {
            const float ma = smask[nt * 8 + cbase]     ? 0.f : -1e30f;
            const float mb = smask[nt * 8 + cbase + 1] ? 0.f : -1e30f;
            sacc[nt][0] = sacc[nt][0] * SCALE_L2E + ma;
            sacc[nt][1] = sacc[nt][1] * SCALE_L2E + mb;
            sacc[nt][2] = sacc[nt][2] * SCALE_L2E + ma;
            sacc[nt][3] = sacc[nt][3] * SCALE_L2E + mb;
        }

        // ---- online softmax (rows r=lane>>2 and r+8), exp2 in-place ----
        float mx0 = -1e30f, mx1 = -1e30f;
#pragma unroll
        for (int nt = 0; nt < 8; ++nt) {
            mx0 = fmaxf(mx0, fmaxf(sacc[nt][0], sacc[nt][1]));
            mx1 = fmaxf(mx1, fmaxf(sacc[nt][2], sacc[nt][3]));
        }
        mx0 = fmaxf(mx0, __shfl_xor_sync(0xffffffffu, mx0, 1));
        mx0 = fmaxf(mx0, __shfl_xor_sync(0xffffffffu, mx0, 2));
        mx1 = fmaxf(mx1, __shfl_xor_sync(0xffffffffu, mx1, 1));
        mx1 = fmaxf(mx1, __shfl_xor_sync(0xffffffffu, mx1, 2));
        const float mn0 = fmaxf(m0s, mx0), mn1 = fmaxf(m1s, mx1);
        const float al0 = exp2f(m0s - mn0), al1 = exp2f(m1s - mn1);
        m0s = mn0; m1s = mn1;

        float rs0 = 0.f, rs1 = 0.f;
#pragma unroll
        for (int nt = 0; nt < 8; ++nt) {
            sacc[nt][0] = exp2f(sacc[nt][0] - mn0);
            sacc[nt][1] = exp2f(sacc[nt][1] - mn0);
            sacc[nt][2] = exp2f(sacc[nt][2] - mn1);
            sacc[nt][3] = exp2f(sacc[nt][3] - mn1);
            rs0 += sacc[nt][0] + sacc[nt][1];
            rs1 += sacc[nt][2] + sacc[nt][3];
        }
        rs0 += __shfl_xor_sync(0xffffffffu, rs0, 1);
        rs0 += __shfl_xor_sync(0xffffffffu, rs0, 2);
        rs1 += __shfl_xor_sync(0xffffffffu, rs1, 1);
        rs1 += __shfl_xor_sync(0xffffffffu, rs1, 2);
        l0s = l0s * al0 + rs0;
        l1s = l1s * al1 + rs1;
#pragma unroll
        for (int nt = 0; nt < 8; ++nt) {
            oacc[nt][0] *= al0; oacc[nt][1] *= al0;
            oacc[nt][2] *= al1; oacc[nt][3] *= al1;
        }

        // ---- O += P @ V : pack P fragment per-kf2 (8 live pack regs) ----
#pragma unroll
        for (int kf2 = 0; kf2 < 4; ++kf2) {
            uint32_t ph4[4], pl4[4];
            split2(sacc[2 * kf2][0],     sacc[2 * kf2][1],     ph4[0], pl4[0]);
            split2(sacc[2 * kf2][2],     sacc[2 * kf2][3],     ph4[1], pl4[1]);
            split2(sacc[2 * kf2 + 1][0], sacc[2 * kf2 + 1][1], ph4[2], pl4[2]);
            split2(sacc[2 * kf2 + 1][2], sacc[2 * kf2 + 1][3], ph4[3], pl4[3]);
#pragma unroll
            for (int dt2 = 0; dt2 < 4; ++dt2) {
                const uint32_t voff =
                    (uint32_t)((kf2 * 16 + vb_r) * GSTR + dt2 * 16 + vb_c8) * 2;
                uint32_t vh4[4], vl4[4];
                ldsm_x4t(vh4, kvb + 18432 + voff);
                ldsm_x4t(vl4, kvb + 27648 + voff);
#pragma unroll
                for (int hh = 0; hh < 2; ++hh) {
                    float* d = oacc[dt2 * 2 + hh];
                    mma16816(d, ph4, vh4 + hh * 2);
                    mma16816(d, ph4, vl4 + hh * 2);
                    mma16816(d, pl4, vh4 + hh * 2);
                }
            }
        }
        __syncthreads();   // done reading buf before refill
    }

    // epilogue: O /= l, split to bf16 hi/lo, write (B,L,D)
    const float inv0 = 1.f / l0s, inv1 = 1.f / l1s;
    const int row0 = qb + mrow + (lane >> 2);
#pragma unroll
    for (int dt = 0; dt < 8; ++dt) {
        const int col = h * DK + dt * 8 + 2 * (lane & 3);
        const size_t i0 = ((size_t)b * SEQLEN + row0) * DMODEL + col;
        const size_t i1 = i0 + (size_t)8 * DMODEL;
        uint32_t hh, ll;
        split2(oacc[dt][0] * inv0, oacc[dt][1] * inv0, hh, ll);
        *(uint32_t*)(g_ohi + i0) = hh; *(uint32_t*)(g_olo + i0) = ll;
        split2(oacc[dt][2] * inv1, oacc[dt][3] * inv1, hh, ll);
        *(uint32_t*)(g_ohi + i1) = hh; *(uint32_t*)(g_olo + i1) = ll;
    }
}

// ==================== launch ====================
extern "C" void kernel_launch(void* const* d_in, const int* in_sizes, int n_in,
                              void* d_out, int out_size)
{
    const float* x     = (const float*)d_in[0];
    const int*   amask = (const int*)  d_in[1];
    const float* w_qkv = (const float*)d_in[2];
    const float* b_qkv = (const float*)d_in[3];
    const float* w_out = (const float*)d_in[4];
    const float* b_out = (const float*)d_in[5];
    float*       out   = (float*)d_out;

    bf16 *xhi, *xlo, *wqh, *wql, *woh, *wol, *ohi, *olo;
    cudaGetSymbolAddress((void**)&xhi, g_xhi);
    cudaGetSymbolAddress((void**)&xlo, g_xlo);
    cudaGetSymbolAddress((void**)&wqh, g_wqh);
    cudaGetSymbolAddress((void**)&wql, g_wql);
    cudaGetSymbolAddress((void**)&woh, g_woh);
    cudaGetSymbolAddress((void**)&wol, g_wol);
    cudaGetSymbolAddress((void**)&ohi, g_ohi);
    cudaGetSymbolAddress((void**)&olo, g_olo);

    // 0) splits / transposes
    const int n4 = MTOT * DMODEL / 4;
    split_x_kernel<<<(n4 + 255) / 256, 256>>>(x, xhi, xlo, n4);
    tsplit_kernel<<<dim3(3 * DMODEL / 32, DMODEL / 32), 256>>>(w_qkv, wqh, wql, DMODEL, 3 * DMODEL);
    tsplit_kernel<<<dim3(DMODEL / 32, DMODEL / 32), 256>>>(w_out, woh, wol, DMODEL, DMODEL);

    // 1) QKV projection (128x64 tiles, occ 2)
    cudaFuncSetAttribute(gemm_mma<1>, cudaFuncAttributeMaxDynamicSharedMemorySize, G_SMEM);
    gemm_mma<1><<<dim3(3 * DMODEL / 64, MTOT / 128), 256, G_SMEM>>>(
        xhi, xlo, wqh, wql, b_qkv, nullptr, 3 * DMODEL, DMODEL);

    // 2) flash attention (occ 2)
    cudaFuncSetAttribute(attn_mma, cudaFuncAttributeMaxDynamicSharedMemorySize, ATT_SMEM);
    attn_mma<<<dim3(SEQLEN / 128, BATCH * NHEADS), 256, ATT_SMEM>>>(amask);

    // 3) output projection (128x64 tiles, occ 2)
    cudaFuncSetAttribute(gemm_mma<0>, cudaFuncAttributeMaxDynamicSharedMemorySize, G_SMEM);
    gemm_mma<0><<<dim3(DMODEL / 64, MTOT / 128), 256, G_SMEM>>>(
        ohi, olo, woh, wol, b_out, out, DMODEL, DMODEL);
}

// round 10
// speedup vs baseline: 1.0853x; 1.0046x over previous
#include <cuda_runtime.h>
#include <cuda_bf16.h>
#include <cstdint>

#define BATCH   2
#define NHEADS  12
#define SEQLEN  2048
#define DMODEL  768
#define DK      64
#define MTOT    (BATCH * SEQLEN)          // 4096

typedef __nv_bfloat16 bf16;

// ---------------- scratch (no allocations allowed) ----------------
__device__ __align__(256) bf16 g_xhi[(size_t)MTOT * DMODEL];
__device__ __align__(256) bf16 g_xlo[(size_t)MTOT * DMODEL];
__device__ __align__(256) bf16 g_wqh[(size_t)3 * DMODEL * DMODEL];  // W_qkv^T [N][K]
__device__ __align__(256) bf16 g_wql[(size_t)3 * DMODEL * DMODEL];
__device__ __align__(256) bf16 g_woh[(size_t)DMODEL * DMODEL];      // W_out^T [N][K]
__device__ __align__(256) bf16 g_wol[(size_t)DMODEL * DMODEL];
__device__ __align__(256) bf16 g_qh[(size_t)BATCH * NHEADS * SEQLEN * DK];
__device__ __align__(256) bf16 g_ql[(size_t)BATCH * NHEADS * SEQLEN * DK];
__device__ __align__(256) bf16 g_kh[(size_t)BATCH * NHEADS * SEQLEN * DK];
__device__ __align__(256) bf16 g_kl[(size_t)BATCH * NHEADS * SEQLEN * DK];
__device__ __align__(256) bf16 g_vh[(size_t)BATCH * NHEADS * SEQLEN * DK];
__device__ __align__(256) bf16 g_vl[(size_t)BATCH * NHEADS * SEQLEN * DK];
__device__ __align__(256) bf16 g_ohi[(size_t)MTOT * DMODEL];
__device__ __align__(256) bf16 g_olo[(size_t)MTOT * DMODEL];

// ==================== helpers ====================
__device__ __forceinline__ uint32_t smem_u32(const void* p) {
    uint32_t a;
    asm("{ .reg .u64 t; cvta.to.shared.u64 t, %1; cvt.u32.u64 %0, t; }" : "=r"(a) : "l"(p));
    return a;
}
__device__ __forceinline__ void mma16816(float* d, const uint32_t* a, const uint32_t* b) {
    asm volatile(
        "mma.sync.aligned.m16n8k16.row.col.f32.bf16.bf16.f32 "
        "{%0,%1,%2,%3}, {%4,%5,%6,%7}, {%8,%9}, {%0,%1,%2,%3};"
        : "+f"(d[0]), "+f"(d[1]), "+f"(d[2]), "+f"(d[3])
        : "r"(a[0]), "r"(a[1]), "r"(a[2]), "r"(a[3]), "r"(b[0]), "r"(b[1]));
}
__device__ __forceinline__ void ldsm_x4(uint32_t* r, uint32_t addr) {
    asm volatile("ldmatrix.sync.aligned.m8n8.x4.shared.b16 {%0,%1,%2,%3}, [%4];"
                 : "=r"(r[0]), "=r"(r[1]), "=r"(r[2]), "=r"(r[3]) : "r"(addr));
}
__device__ __forceinline__ void ldsm_x4t(uint32_t* r, uint32_t addr) {
    asm volatile("ldmatrix.sync.aligned.m8n8.x4.trans.shared.b16 {%0,%1,%2,%3}, [%4];"
                 : "=r"(r[0]), "=r"(r[1]), "=r"(r[2]), "=r"(r[3]) : "r"(addr));
}
__device__ __forceinline__ void cp_async16(uint32_t dst, const void* src) {
    asm volatile("cp.async.cg.shared.global [%0], [%1], 16;" :: "r"(dst), "l"(src));
}
__device__ __forceinline__ void cp_commit() {
    asm volatile("cp.async.commit_group;" ::: "memory");
}
template <int N>
__device__ __forceinline__ void cp_wait() {
    asm volatile("cp.async.wait_group %0;" :: "n"(N) : "memory");
}
// split (x,y) fp32 -> packed bf16 hi pair + bf16 lo (residual) pair
__device__ __forceinline__ void split2(float x, float y, uint32_t& h, uint32_t& l) {
    __nv_bfloat162 hh = __floats2bfloat162_rn(x, y);
    float rx = x - __bfloat162float(hh.x);
    float ry = y - __bfloat162float(hh.y);
    __nv_bfloat162 ll = __floats2bfloat162_rn(rx, ry);
    h = *reinterpret_cast<uint32_t*>(&hh);
    l = *reinterpret_cast<uint32_t*>(&ll);
}

// ==================== prep kernels ====================
__global__ void split_x_kernel(const float* __restrict__ x,
                               bf16* __restrict__ hi, bf16* __restrict__ lo, int n4)
{
    int i = blockIdx.x * blockDim.x + threadIdx.x;
    if (i >= n4) return;
    float4 v = ((const float4*)x)[i];
    uint32_t h0, l0, h1, l1;
    split2(v.x, v.y, h0, l0);
    split2(v.z, v.w, h1, l1);
    ((uint32_t*)hi)[i * 2 + 0] = h0;
    ((uint32_t*)hi)[i * 2 + 1] = h1;
    ((uint32_t*)lo)[i * 2 + 0] = l0;
    ((uint32_t*)lo)[i * 2 + 1] = l1;
}

// transpose W(K,N) -> T(N,K) and split into bf16 hi/lo
__global__ void tsplit_kernel(const float* __restrict__ W,
                              bf16* __restrict__ Th, bf16* __restrict__ Tl,
                              int K, int N)
{
    __shared__ float t[32][33];
    const int tx = threadIdx.x & 31, ty = threadIdx.x >> 5;   // 256 threads
    const int bn = blockIdx.x * 32, bk = blockIdx.y * 32;
#pragma unroll
    for (int j = 0; j < 4; ++j)
        t[ty + j * 8][tx] = W[(size_t)(bk + ty + j * 8) * N + bn + tx];
    __syncthreads();
#pragma unroll
    for (int j = 0; j < 4; ++j) {
        const int n = bn + ty + j * 8;
        const int k = bk + tx;
        const float v = t[tx][ty + j * 8];
        bf16 h = __float2bfloat16(v);
        bf16 l = __float2bfloat16(v - __bfloat162float(h));
        Th[(size_t)n * K + k] = h;
        Tl[(size_t)n * K + k] = l;
    }
}

// ==================== mma.sync bf16x3 GEMM (128x64 tile, occ 2) =========
// Split-term-major MMA ordering: per k-step, pass1 = hi*hi over all 8
// accumulators, pass2 = hi*lo, pass3 = lo*hi. Same-d reuse distance 8.
#define GSTR 72
#define G_STAGE 55296                     // Ah 0 | Al 18432 | Bh 36864 | Bl 46080
#define G_SMEM  (2 * G_STAGE)             // 110592 B

__device__ __forceinline__ void gemm_issue(
    uint32_t sb, int tid, const bf16* Ah, const bf16* Al,
    const bf16* Bh, const bf16* Bl, int m0, int n0, int kc, int K)
{
#pragma unroll
    for (int i = 0; i < 12; ++i) {
        const int idx = i * 256 + tid;       // 0..3071
        uint32_t dst; const bf16* src; int grow, seg;
        if (idx < 2048) {                    // A hi/lo: 2 arrays x 1024
            const int arr = idx >> 10, rem = idx & 1023;
            const int row = rem >> 3; seg = rem & 7;
            src = arr ? Al : Ah; grow = m0 + row;
            dst = sb + arr * 18432 + (uint32_t)(row * GSTR + seg * 8) * 2;
        } else {                             // B hi/lo: 2 arrays x 512
            const int j = idx - 2048;
            const int arr = j >> 9, rem = j & 511;
            const int row = rem >> 3; seg = rem & 7;
            src = arr ? Bl : Bh; grow = n0 + row;
            dst = sb + 36864 + arr * 9216 + (uint32_t)(row * GSTR + seg * 8) * 2;
        }
        cp_async16(dst, src + (size_t)grow * K + kc + seg * 8);
    }
    cp_commit();
}

template <int MODE>
__global__ __launch_bounds__(256, 2)
void gemm_mma(const bf16* __restrict__ Ah, const bf16* __restrict__ Al,
              const bf16* __restrict__ Bh, const bf16* __restrict__ Bl,
              const float* __restrict__ bias, float* __restrict__ out,
              int N, int K)
{
    extern __shared__ char smc[];
    const uint32_t base = smem_u32(smc);

    const int tid = threadIdx.x, lane = tid & 31, wid = tid >> 5;
    const int wm = wid & 3, wn = wid >> 2;        // 4m x 2n
    const int m0 = blockIdx.y * 128, n0 = blockIdx.x * 64;

    float acc[2][4][4];
#pragma unroll
    for (int t = 0; t < 2; ++t)
#pragma unroll
        for (int n = 0; n < 4; ++n)
#pragma unroll
            for (int j = 0; j < 4; ++j) acc[t][n][j] = 0.f;

    const int a_r  = lane & 15;
    const int a_c8 = (lane >> 4) * 8;
    const int b_r  = (lane & 7) + ((lane >> 4) << 3);
    const int b_c8 = ((lane >> 3) & 1) * 8;

    const int NC = K / 64;                  // 12
    gemm_issue(base, tid, Ah, Al, Bh, Bl, m0, n0, 0, K);   // G0 -> stage 0

    for (int c = 0; c < NC; ++c) {
        const int buf = c & 1;
        if (c + 1 < NC) {
            gemm_issue(base + (buf ^ 1) * G_STAGE, tid, Ah, Al, Bh, Bl,
                       m0, n0, (c + 1) * 64, K);
            cp_wait<1>();
        } else {
            cp_wait<0>();
        }
        __syncthreads();

        const uint32_t sb = base + buf * G_STAGE;
#pragma unroll
        for (int kf = 0; kf < 4; ++kf) {
            // load ALL fragments for this k-step
            uint32_t ah[2][4], al[2][4], bh2[2][4], bl2[2][4];
#pragma unroll
            for (int t = 0; t < 2; ++t) {
                const uint32_t off =
                    (uint32_t)((wm * 32 + t * 16 + a_r) * GSTR + kf * 16 + a_c8) * 2;
                ldsm_x4(ah[t], sb + off);
                ldsm_x4(al[t], sb + 18432 + off);
            }
#pragma unroll
            for (int nt2 = 0; nt2 < 2; ++nt2) {
                const uint32_t off =
                    (uint32_t)((wn * 32 + nt2 * 16 + b_r) * GSTR + kf * 16 + b_c8) * 2;
                ldsm_x4(bh2[nt2], sb + 36864 + off);
                ldsm_x4(bl2[nt2], sb + 46080 + off);
            }
            // pass 1: hi*hi  (8 independent accumulators)
#pragma unroll
            for (int t = 0; t < 2; ++t)
#pragma unroll
                for (int nt2 = 0; nt2 < 2; ++nt2)
#pragma unroll
                    for (int h = 0; h < 2; ++h)
                        mma16816(acc[t][nt2 * 2 + h], ah[t], bh2[nt2] + h * 2);
            // pass 2: hi*lo
#pragma unroll
            for (int t = 0; t < 2; ++t)
#pragma unroll
                for (int nt2 = 0; nt2 < 2; ++nt2)
#pragma unroll
                    for (int h = 0; h < 2; ++h)
                        mma16816(acc[t][nt2 * 2 + h], ah[t], bl2[nt2] + h * 2);
            // pass 3: lo*hi
#pragma unroll
            for (int t = 0; t < 2; ++t)
#pragma unroll
                for (int nt2 = 0; nt2 < 2; ++nt2)
#pragma unroll
                    for (int h = 0; h < 2; ++h)
                        mma16816(acc[t][nt2 * 2 + h], al[t], bh2[nt2] + h * 2);
        }
        __syncthreads();   // readers done before this stage is refilled
    }

    // epilogue
#pragma unroll
    for (int t = 0; t < 2; ++t) {
        const int gr0 = m0 + wm * 32 + t * 16 + (lane >> 2);
#pragma unroll
        for (int nt = 0; nt < 4; ++nt) {
            const int gn = n0 + wn * 32 + nt * 8 + 2 * (lane & 3);
            const float b0 = bias[gn], b1 = bias[gn + 1];
            const float v00 = acc[t][nt][0] + b0, v01 = acc[t][nt][1] + b1;
            const float v10 = acc[t][nt][2] + b0, v11 = acc[t][nt][3] + b1;
            if (MODE == 0) {
                *(float2*)&out[(size_t)gr0 * N + gn]       = make_float2(v00, v01);
                *(float2*)&out[(size_t)(gr0 + 8) * N + gn] = make_float2(v10, v11);
            } else {
                const int part = gn / DMODEL;
                const int w = gn % DMODEL;
                const int hh = w >> 6, dd = w & 63;
                bf16* dh = (part == 0) ? g_qh : (part == 1) ? g_kh : g_vh;
                bf16* dl = (part == 0) ? g_ql : (part == 1) ? g_kl : g_vl;
                const int bb = gr0 >> 11;
                const int ll0 = gr0 & 2047;
                const size_t i0 = (((size_t)bb * NHEADS + hh) * SEQLEN + ll0) * DK + dd;
                const size_t i1 = i0 + 8 * DK;
                uint32_t ph, pl;
                split2(v00, v01, ph, pl);
                *(uint32_t*)(dh + i0) = ph; *(uint32_t*)(dl + i0) = pl;
                split2(v10, v11, ph, pl);
                *(uint32_t*)(dh + i1) = ph; *(uint32_t*)(dl + i1) = pl;
            }
        }
    }
}

// ==================== flash attention via mma.sync (bf16x3, occ 2) ======
// BM=128, BN=64, 256 thr / 8 warps; 2 KV stages; split-term-major MMA
// ordering with nt2/dt2 pairs (same-d distance 4).
#define KV_STAGE  36864
#define ATT_MASK  110592
#define ATT_SMEM  (110592 + 512)
#define SCALE_L2E 0.1803368867f           // 0.125 * log2(e)

__device__ __forceinline__ void attn_issue_kv(
    uint32_t base, int tid, const bf16* Kh, const bf16* Kl,
    const bf16* Vh, const bf16* Vl, const int* amask_row, int kb, int buf)
{
    const uint32_t sb = base + 36864 + buf * KV_STAGE;
#pragma unroll
    for (int i = 0; i < 8; ++i) {
        const int idx = i * 256 + tid;      // 4 arrays x 512
        const int arr = idx >> 9;
        const int rem = idx & 511;
        const int row = rem >> 3, seg = rem & 7;
        const bf16* src = (arr == 0) ? Kh : (arr == 1) ? Kl : (arr == 2) ? Vh : Vl;
        cp_async16(sb + arr * 9216 + (uint32_t)(row * GSTR + seg * 8) * 2,
                   src + (size_t)(kb + row) * DK + seg * 8);
    }
    if (tid < 16)
        cp_async16(base + ATT_MASK + buf * 256 + tid * 16, amask_row + kb + tid * 4);
    cp_commit();
}

__global__ __launch_bounds__(256, 2)
void attn_mma(const int* __restrict__ amask)
{
    extern __shared__ char smc[];
    const uint32_t base = smem_u32(smc);

    const int tid = threadIdx.x, lane = tid & 31, wid = tid >> 5;
    const int bh = blockIdx.y, b = bh / NHEADS, h = bh % NHEADS;
    const int qb = blockIdx.x * 128;

    const bf16* Qh = g_qh + (size_t)bh * SEQLEN * DK;
    const bf16* Ql = g_ql + (size_t)bh * SEQLEN * DK;
    const bf16* Kh = g_kh + (size_t)bh * SEQLEN * DK;
    const bf16* Kl = g_kl + (size_t)bh * SEQLEN * DK;
    const bf16* Vh = g_vh + (size_t)bh * SEQLEN * DK;
    const bf16* Vl = g_vl + (size_t)bh * SEQLEN * DK;
    const int* amask_row = amask + (size_t)b * SEQLEN;

    // prologue G0: Q (hi/lo) + KV chunk 0 + mask 0 (single commit)
#pragma unroll
    for (int i = 0; i < 8; ++i) {
        const int idx = i * 256 + tid;          // 0..2047
        const int arr = idx >> 10;              // 0 hi, 1 lo
        const int rem = idx & 1023;
        const int row = rem >> 3, seg = rem & 7;
        const bf16* src = arr ? Ql : Qh;
        cp_async16(base + arr * 18432 + (uint32_t)(row * GSTR + seg * 8) * 2,
                   src + (size_t)(qb + row) * DK + seg * 8);
    }
    attn_issue_kv(base, tid, Kh, Kl, Vh, Vl, amask_row, 0, 0);

    float m0s = -1e30f, m1s = -1e30f, l0s = 0.f, l1s = 0.f;
    float oacc[8][4];
#pragma unroll
    for (int n = 0; n < 8; ++n)
#pragma unroll
        for (int j = 0; j < 4; ++j) oacc[n][j] = 0.f;

    const int a_r  = lane & 15;
    const int a_c8 = (lane >> 4) * 8;
    const int kb_r = (lane & 7) + ((lane >> 4) << 3);
    const int kb_c8 = ((lane >> 3) & 1) * 8;
    const int vb_r = (lane & 7) + ((lane >> 3) & 1) * 8;
    const int vb_c8 = (lane >> 4) * 8;
    const int mrow = wid * 16;
    const int cbase = 2 * (lane & 3);

    const int NIT = SEQLEN / 64;   // 32
    for (int it = 0; it < NIT; ++it) {
        const int buf = it & 1;
        if (it + 1 < NIT) {
            attn_issue_kv(base, tid, Kh, Kl, Vh, Vl, amask_row, (it + 1) * 64, buf ^ 1);
            cp_wait<1>();
        } else {
            cp_wait<0>();
        }
        __syncthreads();

        const uint32_t kvb = base + 36864 + buf * KV_STAGE;
        const int* smask = (const int*)(smc + ATT_MASK + buf * 256);

        // ---- S = Q @ K^T (split-term-major, nt2 pairs) ----
        float sacc[8][4];
#pragma unroll
        for (int n = 0; n < 8; ++n)
#pragma unroll
            for (int j = 0; j < 4; ++j) sacc[n][j] = 0.f;

#pragma unroll
        for (int kf = 0; kf < 4; ++kf) {
            uint32_t qh4[4], ql4[4];
            const uint32_t qoff = (uint32_t)((mrow + a_r) * GSTR + kf * 16 + a_c8) * 2;
            ldsm_x4(qh4, base + qoff);
            ldsm_x4(ql4, base + 18432 + qoff);
#pragma unroll
            for (int np = 0; np < 2; ++np) {             // nt2 pair {2np, 2np+1}
                uint32_t kh4[2][4], kl4[2][4];
#pragma unroll
                for (int j = 0; j < 2; ++j) {
                    const int nt2 = np * 2 + j;
                    const uint32_t koff =
                        (uint32_t)((nt2 * 16 + kb_r) * GSTR + kf * 16 + kb_c8) * 2;
                    ldsm_x4(kh4[j], kvb + koff);
                    ldsm_x4(kl4[j], kvb + 9216 + koff);
                }
                float* d[4] = {sacc[np * 4 + 0], sacc[np * 4 + 1],
                               sacc[np * 4 + 2], sacc[np * 4 + 3]};
                // pass 1: qh*kh
#pragma unroll
                for (int j = 0; j < 2; ++j)
#pragma unroll
                    for (int hh = 0; hh < 2; ++hh)
                        mma16816(d[j * 2 + hh], qh4, kh4[j] + hh * 2);
                // pass 2: qh*kl
#pragma unroll
                for (int j = 0; j < 2; ++j)
#pragma unroll
                    for (int hh = 0; hh < 2; ++hh)
                        mma16816(d[j * 2 + hh], qh4, kl4[j] + hh * 2);
                // pass 3: ql*kh
#pragma unroll
                for (int j = 0; j < 2; ++j)
#pragma unroll
                    for (int hh = 0; hh < 2; ++hh)
                        mma16816(d[j * 2 + hh], ql4, kh4[j] + hh * 2);
            }
        }

        // ---- scale (log2 domain) + mask ----
#pragma unroll
        for (int nt = 0; nt < 8; ++nt) {
            const float ma = smask[nt * 8 + cbase]     ? 0.f : -1e30f;
            const float mb = smask[nt * 8 + cbase + 1] ? 0.f : -1e30f;
            sacc[nt][0] = sacc[nt][0] * SCALE_L2E + ma;
            sacc[nt][1] = sacc[nt][1] * SCALE_L2E + mb;
            sacc[nt][2] = sacc[nt][2] * SCALE_L2E + ma;
            sacc[nt][3] = sacc[nt][3] * SCALE_L2E + mb;
        }

        // ---- online softmax (rows r=lane>>2 and r+8), exp2 in-place ----
        float mx0 = -1e30f, mx1 = -1e30f;
#pragma unroll
        for (int nt = 0; nt < 8; ++nt) {
            mx0 = fmaxf(mx0, fmaxf(sacc[nt][0], sacc[nt][1]));
            mx1 = fmaxf(mx1, fmaxf(sacc[nt][2], sacc[nt][3]));
        }
        mx0 = fmaxf(mx0, __shfl_xor_sync(0xffffffffu, mx0, 1));
        mx0 = fmaxf(mx0, __shfl_xor_sync(0xffffffffu, mx0, 2));
        mx1 = fmaxf(mx1, __shfl_xor_sync(0xffffffffu, mx1, 1));
        mx1 = fmaxf(mx1, __shfl_xor_sync(0xffffffffu, mx1, 2));
        const float mn0 = fmaxf(m0s, mx0), mn1 = fmaxf(m1s, mx1);
        const float al0 = exp2f(m0s - mn0), al1 = exp2f(m1s - mn1);
        m0s = mn0; m1s = mn1;

        float rs0 = 0.f, rs1 = 0.f;
#pragma unroll
        for (int nt = 0; nt < 8; ++nt) {
            sacc[nt][0] = exp2f(sacc[nt][0] - mn0);
            sacc[nt][1] = exp2f(sacc[nt][1] - mn0);
            sacc[nt][2] = exp2f(sacc[nt][2] - mn1);
            sacc[nt][3] = exp2f(sacc[nt][3] - mn1);
            rs0 += sacc[nt][0] + sacc[nt][1];
            rs1 += sacc[nt][2] + sacc[nt][3];
        }
        rs0 += __shfl_xor_sync(0xffffffffu, rs0, 1);
        rs0 += __shfl_xor_sync(0xffffffffu, rs0, 2);
        rs1 += __shfl_xor_sync(0xffffffffu, rs1, 1);
        rs1 += __shfl_xor_sync(0xffffffffu, rs1, 2);
        l0s = l0s * al0 + rs0;
        l1s = l1s * al1 + rs1;
#pragma unroll
        for (int nt = 0; nt < 8; ++nt) {
            oacc[nt][0] *= al0; oacc[nt][1] *= al0;
            oacc[nt][2] *= al1; oacc[nt][3] *= al1;
        }

        // ---- O += P @ V (split-term-major, dt2 pairs) ----
#pragma unroll
        for (int kf2 = 0; kf2 < 4; ++kf2) {
            uint32_t ph4[4], pl4[4];
            split2(sacc[2 * kf2][0],     sacc[2 * kf2][1],     ph4[0], pl4[0]);
            split2(sacc[2 * kf2][2],     sacc[2 * kf2][3],     ph4[1], pl4[1]);
            split2(sacc[2 * kf2 + 1][0], sacc[2 * kf2 + 1][1], ph4[2], pl4[2]);
            split2(sacc[2 * kf2 + 1][2], sacc[2 * kf2 + 1][3], ph4[3], pl4[3]);
#pragma unroll
            for (int dp = 0; dp < 2; ++dp) {             // dt2 pair {2dp, 2dp+1}
                uint32_t vh4[2][4], vl4[2][4];
#pragma unroll
                for (int j = 0; j < 2; ++j) {
                    const int dt2 = dp * 2 + j;
                    const uint32_t voff =
                        (uint32_t)((kf2 * 16 + vb_r) * GSTR + dt2 * 16 + vb_c8) * 2;
                    ldsm_x4t(vh4[j], kvb + 18432 + voff);
                    ldsm_x4t(vl4[j], kvb + 27648 + voff);
                }
                float* d[4] = {oacc[dp * 4 + 0], oacc[dp * 4 + 1],
                               oacc[dp * 4 + 2], oacc[dp * 4 + 3]};
                // pass 1: ph*vh
#pragma unroll
                for (int j = 0; j < 2; ++j)
#pragma unroll
                    for (int hh = 0; hh < 2; ++hh)
                        mma16816(d[j * 2 + hh], ph4, vh4[j] + hh * 2);
                // pass 2: ph*vl
#pragma unroll
                for (int j = 0; j < 2; ++j)
#pragma unroll
                    for (int hh = 0; hh < 2; ++hh)
                        mma16816(d[j * 2 + hh], ph4, vl4[j] + hh * 2);
                // pass 3: pl*vh
#pragma unroll
                for (int j = 0; j < 2; ++j)
#pragma unroll
                    for (int hh = 0; hh < 2; ++hh)
                        mma16816(d[j * 2 + hh], pl4, vh4[j] + hh * 2);
            }
        }
        __syncthreads();   // done reading buf before refill
    }

    // epilogue: O /= l, split to bf16 hi/lo, write (B,L,D)
    const float inv0 = 1.f / l0s, inv1 = 1.f / l1s;
    const int row0 = qb + mrow + (lane >> 2);
#pragma unroll
    for (int dt = 0; dt < 8; ++dt) {
        const int col = h * DK + dt * 8 + 2 * (lane & 3);
        const size_t i0 = ((size_t)b * SEQLEN + row0) * DMODEL + col;
        const size_t i1 = i0 + (size_t)8 * DMODEL;
        uint32_t hh, ll;
        split2(oacc[dt][0] * inv0, oacc[dt][1] * inv0, hh, ll);
        *(uint32_t*)(g_ohi + i0) = hh; *(uint32_t*)(g_olo + i0) = ll;
        split2(oacc[dt][2] * inv1, oacc[dt][3] * inv1, hh, ll);
        *(uint32_t*)(g_ohi + i1) = hh; *(uint32_t*)(g_olo + i1) = ll;
    }
}

// ==================== launch ====================
extern "C" void kernel_launch(void* const* d_in, const int* in_sizes, int n_in,
                              void* d_out, int out_size)
{
    const float* x     = (const float*)d_in[0];
    const int*   amask = (const int*)  d_in[1];
    const float* w_qkv = (const float*)d_in[2];
    const float* b_qkv = (const float*)d_in[3];
    const float* w_out = (const float*)d_in[4];
    const float* b_out = (const float*)d_in[5];
    float*       out   = (float*)d_out;

    bf16 *xhi, *xlo, *wqh, *wql, *woh, *wol, *ohi, *olo;
    cudaGetSymbolAddress((void**)&xhi, g_xhi);
    cudaGetSymbolAddress((void**)&xlo, g_xlo);
    cudaGetSymbolAddress((void**)&wqh, g_wqh);
    cudaGetSymbolAddress((void**)&wql, g_wql);
    cudaGetSymbolAddress((void**)&woh, g_woh);
    cudaGetSymbolAddress((void**)&wol, g_wol);
    cudaGetSymbolAddress((void**)&ohi, g_ohi);
    cudaGetSymbolAddress((void**)&olo, g_olo);

    // 0) splits / transposes
    const int n4 = MTOT * DMODEL / 4;
    split_x_kernel<<<(n4 + 255) / 256, 256>>>(x, xhi, xlo, n4);
    tsplit_kernel<<<dim3(3 * DMODEL / 32, DMODEL / 32), 256>>>(w_qkv, wqh, wql, DMODEL, 3 * DMODEL);
    tsplit_kernel<<<dim3(DMODEL / 32, DMODEL / 32), 256>>>(w_out, woh, wol, DMODEL, DMODEL);

    // 1) QKV projection (128x64 tiles, occ 2)
    cudaFuncSetAttribute(gemm_mma<1>, cudaFuncAttributeMaxDynamicSharedMemorySize, G_SMEM);
    gemm_mma<1><<<dim3(3 * DMODEL / 64, MTOT / 128), 256, G_SMEM>>>(
        xhi, xlo, wqh, wql, b_qkv, nullptr, 3 * DMODEL, DMODEL);

    // 2) flash attention (occ 2)
    cudaFuncSetAttribute(attn_mma, cudaFuncAttributeMaxDynamicSharedMemorySize, ATT_SMEM);
    attn_mma<<<dim3(SEQLEN / 128, BATCH * NHEADS), 256, ATT_SMEM>>>(amask);

    // 3) output projection (128x64 tiles, occ 2)
    cudaFuncSetAttribute(gemm_mma<0>, cudaFuncAttributeMaxDynamicSharedMemorySize, G_SMEM);
    gemm_mma<0><<<dim3(DMODEL / 64, MTOT / 128), 256, G_SMEM>>>(
        ohi, olo, woh, wol, b_out, out, DMODEL, DMODEL);
}